// round 14
// baseline (speedup 1.0000x reference)
#include <cuda_runtime.h>
#include <cuda_fp16.h>
#include <cstdint>

#define NE 32
#define NH 2048
#define NI 768
#define TWO_I 1536
#define NK 4
#define NT 2048
#define TKP 8192
#define PADS 12288
#define MAXTT 128
#define BM 128
#define KC 32
#define ASTR 40
#define BSTR 72

// ---------------- device scratch ---------------------------------------------
__device__ int   g_cnt[NE];
__device__ int   g_cur[NE];
__device__ int   g_tok[PADS];
__device__ float g_w[PADS];
__device__ int   g_is64;
__device__ int   g_tile_e[MAXTT];
__device__ int   g_tile_base[MAXTT];
__device__ __half g_xh[(size_t)NT * NH];      // fp16 pre-converted hidden states
__device__ __half g_i[(size_t)PADS * NI];     // fp16 intermediate

// ---------------- helpers -----------------------------------------------------
__device__ __forceinline__ uint32_t smem_u32(const void* p) {
    uint32_t a;
    asm("{ .reg .u64 t; cvta.to.shared.u64 t, %1; cvt.u32.u64 %0, t; }" : "=r"(a) : "l"(p));
    return a;
}
__device__ __forceinline__ void ldm_x4(uint32_t* r, uint32_t addr) {
    asm volatile("ldmatrix.sync.aligned.m8n8.x4.shared.b16 {%0,%1,%2,%3}, [%4];"
        : "=r"(r[0]), "=r"(r[1]), "=r"(r[2]), "=r"(r[3]) : "r"(addr));
}
__device__ __forceinline__ void ldm_x4t(uint32_t* r, uint32_t addr) {
    asm volatile("ldmatrix.sync.aligned.m8n8.x4.trans.shared.b16 {%0,%1,%2,%3}, [%4];"
        : "=r"(r[0]), "=r"(r[1]), "=r"(r[2]), "=r"(r[3]) : "r"(addr));
}
__device__ __forceinline__ void mma_fp16(float* d, const uint32_t* a, const uint32_t* b) {
    asm volatile("mma.sync.aligned.m16n8k16.row.col.f32.f16.f16.f32 "
        "{%0,%1,%2,%3}, {%4,%5,%6,%7}, {%8,%9}, {%0,%1,%2,%3};"
        : "+f"(d[0]), "+f"(d[1]), "+f"(d[2]), "+f"(d[3])
        : "r"(a[0]), "r"(a[1]), "r"(a[2]), "r"(a[3]), "r"(b[0]), "r"(b[1]));
}
__device__ __forceinline__ uint32_t pk2(float f0, float f1) {
    __half2 h = __floats2half2_rn(f0, f1);
    return *reinterpret_cast<uint32_t*>(&h);
}
__device__ __forceinline__ float silu_f(float v) { return v / (1.0f + __expf(-v)); }

__device__ __forceinline__ int fetch_idx(const int* __restrict__ idx, int i, int is64) {
    return is64 ? idx[2 * i] : idx[i];
}
__device__ __forceinline__ int keep_pair(const int* __restrict__ idx, int t, int k,
                                         int e, int is64) {
    for (int k2 = k + 1; k2 < NK; k2++)
        if (fetch_idx(idx, t * NK + k2, is64) == e) return 0;
    return 1;
}

// ---------------- x fp32->fp16 + routing init (one kernel) --------------------
__global__ void k_xc(const float* __restrict__ x, const int* __restrict__ idx) {
    int i = blockIdx.x * blockDim.x + threadIdx.x;     // one thread = 8 elements
    const float4* p = (const float4*)(x + (size_t)i * 8);
    float4 v0 = p[0], v1 = p[1];
    uint4 o;
    o.x = pk2(v0.x, v0.y); o.y = pk2(v0.z, v0.w);
    o.z = pk2(v1.x, v1.y); o.w = pk2(v1.z, v1.w);
    *(uint4*)(g_xh + (size_t)i * 8) = o;
    if (i < PADS) { g_tok[i] = 0; g_w[i] = 0.f; }
    if (i < NE) g_cnt[i] = 0;
    if (i == 0) {
        int ok = 1;
        for (int j = 0; j < 64; j++) if (idx[2 * j + 1] != 0) { ok = 0; break; }
        g_is64 = ok;
    }
}
__global__ void k_r1(const int* __restrict__ idx) {
    int i = blockIdx.x * blockDim.x + threadIdx.x;
    if (i < TKP) {
        int is64 = g_is64;
        int t = i / NK, k = i % NK;
        int e = fetch_idx(idx, i, is64);
        if (keep_pair(idx, t, k, e, is64)) atomicAdd(&g_cnt[e], 1);
    }
}
__global__ void k_r2(const int* __restrict__ idx, const float* __restrict__ wgt) {
    int tid = threadIdx.x;
    if (tid == 0) {
        int pb = 0, tl = 0;
        for (int e = 0; e < NE; e++) {
            g_cur[e] = pb;
            int nt = (g_cnt[e] + BM - 1) / BM;
            for (int j = 0; j < nt; j++) { g_tile_e[tl] = e; g_tile_base[tl] = pb + j * BM; tl++; }
            pb += nt * BM;
        }
        for (int t2 = tl; t2 < MAXTT; t2++) g_tile_e[t2] = -1;
    }
    __syncthreads();
    int is64 = g_is64;
    for (int i = tid; i < TKP; i += blockDim.x) {
        int t = i / NK, k = i % NK;
        int e = fetch_idx(idx, i, is64);
        if (keep_pair(idx, t, k, e, is64)) {
            int pos = atomicAdd(&g_cur[e], 1);
            g_tok[pos] = t; g_w[pos] = wgt[i];
        }
    }
}

// ---------------- GEMM1: inter = silu(x@Wg)*(x@Wu)*w (fp16) -------------------
__global__ __launch_bounds__(256, 2)
void k_gemm1(const float* __restrict__ W1) {
    int tile = blockIdx.y;
    int e = g_tile_e[tile];
    if (e < 0) return;
    int base = g_tile_base[tile];
    int j0 = blockIdx.x * 64;

    __shared__ __align__(16) __half Ab[2][BM * ASTR];
    __shared__ __align__(16) __half Bgb[2][KC * BSTR];
    __shared__ __align__(16) __half Bub[2][KC * BSTR];

    int tid = threadIdx.x, lane = tid & 31, wid = tid >> 5;
    int wm = wid & 3, wn = wid >> 2;

    const float* W = W1 + (size_t)e * NH * TWO_I;

    int arow = tid >> 1, akp = (tid & 1) * 16;
    const __half* xrowh = g_xh + (size_t)g_tok[base + arow] * NH + akp;
    int bkr = tid >> 3, bc = (tid & 7) * 8;
    const float* wbase = W + (size_t)bkr * TWO_I + j0 + bc;
    int oA = arow * ASTR + akp;
    int oB = bkr * BSTR + bc;

    uint32_t sA[2] = { smem_u32(Ab[0]), smem_u32(Ab[1]) };
    uint32_t sBg[2] = { smem_u32(Bgb[0]), smem_u32(Bgb[1]) };
    uint32_t sBu[2] = { smem_u32(Bub[0]), smem_u32(Bub[1]) };

    uint32_t aoff[2], boff[2];
#pragma unroll
    for (int mf = 0; mf < 2; mf++)
        aoff[mf] = (uint32_t)((wm * 32 + mf * 16 + (lane & 15)) * (ASTR * 2) + (lane >> 4) * 16);
#pragma unroll
    for (int nb = 0; nb < 2; nb++)
        boff[nb] = (uint32_t)((lane & 15) * (BSTR * 2) + (wn * 32 + nb * 16 + (lane >> 4) * 8) * 2);

    float accg[2][4][4] = {}, accu[2][4][4] = {};
    const int NC = NH / KC;

    // ---- prologue: load+convert chunk 0 into buf 0 ----
    {
        const uint4* pa = (const uint4*)xrowh;
        uint4 va0 = pa[0], va1 = pa[1];
        float4 gg0 = *(const float4*)wbase,        gg1 = *(const float4*)(wbase + 4);
        float4 uu0 = *(const float4*)(wbase + NI), uu1 = *(const float4*)(wbase + NI + 4);
        *(uint4*)&Ab[0][oA]     = va0;
        *(uint4*)&Ab[0][oA + 8] = va1;
        *(uint32_t*)&Bgb[0][oB + 0] = pk2(gg0.x, gg0.y);
        *(uint32_t*)&Bgb[0][oB + 2] = pk2(gg0.z, gg0.w);
        *(uint32_t*)&Bgb[0][oB + 4] = pk2(gg1.x, gg1.y);
        *(uint32_t*)&Bgb[0][oB + 6] = pk2(gg1.z, gg1.w);
        *(uint32_t*)&Bub[0][oB + 0] = pk2(uu0.x, uu0.y);
        *(uint32_t*)&Bub[0][oB + 2] = pk2(uu0.z, uu0.w);
        *(uint32_t*)&Bub[0][oB + 4] = pk2(uu1.x, uu1.y);
        *(uint32_t*)&Bub[0][oB + 6] = pk2(uu1.z, uu1.w);
    }
    __syncthreads();

    for (int c = 0; c < NC; c++) {
        int st = c & 1, ns = st ^ 1;
        bool more = (c + 1 < NC);
        // ---- 1) issue LDGs for chunk c+1 (fly over the MMA below) ----
        uint4 va0, va1; float4 gg0, gg1, uu0, uu1;
        if (more) {
            int k0 = (c + 1) * KC;
            const uint4* pa = (const uint4*)(xrowh + k0);
            va0 = pa[0]; va1 = pa[1];
            const float* pg = wbase + (size_t)k0 * TWO_I;
            gg0 = *(const float4*)pg;        gg1 = *(const float4*)(pg + 4);
            uu0 = *(const float4*)(pg + NI); uu1 = *(const float4*)(pg + NI + 4);
        }
        // ---- 2) MMA on chunk c from buf[st] ----
#pragma unroll
        for (int s = 0; s < 2; s++) {
            uint32_t ah[2][4], bg[2][4], bu[2][4];
            uint32_t as_ = (uint32_t)(s * 32), bs_ = (uint32_t)(s * 16 * BSTR * 2);
            ldm_x4(ah[0], sA[st] + aoff[0] + as_);
            ldm_x4(ah[1], sA[st] + aoff[1] + as_);
            ldm_x4t(bg[0], sBg[st] + boff[0] + bs_);
            ldm_x4t(bg[1], sBg[st] + boff[1] + bs_);
            ldm_x4t(bu[0], sBu[st] + boff[0] + bs_);
            ldm_x4t(bu[1], sBu[st] + boff[1] + bs_);
#pragma unroll
            for (int mf = 0; mf < 2; mf++)
#pragma unroll
                for (int nb = 0; nb < 2; nb++)
#pragma unroll
                    for (int f = 0; f < 2; f++) {
                        mma_fp16(accg[mf][nb * 2 + f], ah[mf], &bg[nb][f * 2]);
                        mma_fp16(accu[mf][nb * 2 + f], ah[mf], &bu[nb][f * 2]);
                    }
        }
        // ---- 3) convert + store chunk c+1 into buf[ns] ----
        if (more) {
            *(uint4*)&Ab[ns][oA]     = va0;
            *(uint4*)&Ab[ns][oA + 8] = va1;
            *(uint32_t*)&Bgb[ns][oB + 0] = pk2(gg0.x, gg0.y);
            *(uint32_t*)&Bgb[ns][oB + 2] = pk2(gg0.z, gg0.w);
            *(uint32_t*)&Bgb[ns][oB + 4] = pk2(gg1.x, gg1.y);
            *(uint32_t*)&Bgb[ns][oB + 6] = pk2(gg1.z, gg1.w);
            *(uint32_t*)&Bub[ns][oB + 0] = pk2(uu0.x, uu0.y);
            *(uint32_t*)&Bub[ns][oB + 2] = pk2(uu0.z, uu0.w);
            *(uint32_t*)&Bub[ns][oB + 4] = pk2(uu1.x, uu1.y);
            *(uint32_t*)&Bub[ns][oB + 6] = pk2(uu1.z, uu1.w);
        }
        __syncthreads();
    }

    // ---- epilogue ----
#pragma unroll
    for (int mf = 0; mf < 2; mf++) {
        int rA = base + wm * 32 + mf * 16 + (lane >> 2);
        float wa = g_w[rA], wb = g_w[rA + 8];
#pragma unroll
        for (int nf = 0; nf < 4; nf++) {
            int col = j0 + wn * 32 + nf * 8 + (lane & 3) * 2;
            float o0 = silu_f(accg[mf][nf][0]) * accu[mf][nf][0] * wa;
            float o1 = silu_f(accg[mf][nf][1]) * accu[mf][nf][1] * wa;
            float o2 = silu_f(accg[mf][nf][2]) * accu[mf][nf][2] * wb;
            float o3 = silu_f(accg[mf][nf][3]) * accu[mf][nf][3] * wb;
            *(uint32_t*)&g_i[(size_t)rA * NI + col]       = pk2(o0, o1);
            *(uint32_t*)&g_i[(size_t)(rA + 8) * NI + col] = pk2(o2, o3);
        }
    }
}

// ---------------- GEMM2: out[t,:] += inter @ W2[e] ----------------------------
__global__ __launch_bounds__(256, 2)
void k_gemm2(const float* __restrict__ W2, float* __restrict__ out) {
    int tile = blockIdx.y;
    int e = g_tile_e[tile];
    if (e < 0) return;
    int base = g_tile_base[tile];
    int n0 = blockIdx.x * 64;

    __shared__ __align__(16) __half Ab[2][BM * ASTR];
    __shared__ __align__(16) __half Bb[2][KC * BSTR];

    int tid = threadIdx.x, lane = tid & 31, wid = tid >> 5;
    int wm = wid & 3, wn = wid >> 2;

    const float* W = W2 + (size_t)e * NI * NH;

    int arow = tid >> 1, akp = (tid & 1) * 16;
    const __half* ip = g_i + (size_t)(base + arow) * NI + akp;
    int bkr = tid >> 3, bc = (tid & 7) * 8;
    const float* wbase = W + (size_t)bkr * NH + n0 + bc;
    int oA = arow * ASTR + akp;
    int oB = bkr * BSTR + bc;

    uint32_t sA[2] = { smem_u32(Ab[0]), smem_u32(Ab[1]) };
    uint32_t sB[2] = { smem_u32(Bb[0]), smem_u32(Bb[1]) };

    uint32_t aoff[2], boff[2];
#pragma unroll
    for (int mf = 0; mf < 2; mf++)
        aoff[mf] = (uint32_t)((wm * 32 + mf * 16 + (lane & 15)) * (ASTR * 2) + (lane >> 4) * 16);
#pragma unroll
    for (int nb = 0; nb < 2; nb++)
        boff[nb] = (uint32_t)((lane & 15) * (BSTR * 2) + (wn * 32 + nb * 16 + (lane >> 4) * 8) * 2);

    float acc[2][4][4] = {};
    const int NC = NI / KC;

    // ---- prologue ----
    {
        const uint4* pa = (const uint4*)ip;
        uint4 v0 = pa[0], v1 = pa[1];
        float4 b0 = *(const float4*)wbase, b1 = *(const float4*)(wbase + 4);
        *(uint4*)&Ab[0][oA]     = v0;
        *(uint4*)&Ab[0][oA + 8] = v1;
        *(uint32_t*)&Bb[0][oB + 0] = pk2(b0.x, b0.y);
        *(uint32_t*)&Bb[0][oB + 2] = pk2(b0.z, b0.w);
        *(uint32_t*)&Bb[0][oB + 4] = pk2(b1.x, b1.y);
        *(uint32_t*)&Bb[0][oB + 6] = pk2(b1.z, b1.w);
    }
    __syncthreads();

    for (int c = 0; c < NC; c++) {
        int st = c & 1, ns = st ^ 1;
        bool more = (c + 1 < NC);
        uint4 v0, v1; float4 b0, b1;
        if (more) {
            int k0 = (c + 1) * KC;
            const uint4* pa = (const uint4*)(ip + k0);
            v0 = pa[0]; v1 = pa[1];
            const float* pb = wbase + (size_t)k0 * NH;
            b0 = *(const float4*)pb; b1 = *(const float4*)(pb + 4);
        }
#pragma unroll
        for (int s = 0; s < 2; s++) {
            uint32_t ah[2][4], bb[2][4];
            uint32_t as_ = (uint32_t)(s * 32), bs_ = (uint32_t)(s * 16 * BSTR * 2);
            ldm_x4(ah[0], sA[st] + aoff[0] + as_);
            ldm_x4(ah[1], sA[st] + aoff[1] + as_);
            ldm_x4t(bb[0], sB[st] + boff[0] + bs_);
            ldm_x4t(bb[1], sB[st] + boff[1] + bs_);
#pragma unroll
            for (int mf = 0; mf < 2; mf++)
#pragma unroll
                for (int nb = 0; nb < 2; nb++)
#pragma unroll
                    for (int f = 0; f < 2; f++)
                        mma_fp16(acc[mf][nb * 2 + f], ah[mf], &bb[nb][f * 2]);
        }
        if (more) {
            *(uint4*)&Ab[ns][oA]     = v0;
            *(uint4*)&Ab[ns][oA + 8] = v1;
            *(uint32_t*)&Bb[ns][oB + 0] = pk2(b0.x, b0.y);
            *(uint32_t*)&Bb[ns][oB + 2] = pk2(b0.z, b0.w);
            *(uint32_t*)&Bb[ns][oB + 4] = pk2(b1.x, b1.y);
            *(uint32_t*)&Bb[ns][oB + 6] = pk2(b1.z, b1.w);
        }
        __syncthreads();
    }

#pragma unroll
    for (int mf = 0; mf < 2; mf++) {
        int rA = base + wm * 32 + mf * 16 + (lane >> 2);
        int tA = g_tok[rA], tB = g_tok[rA + 8];
#pragma unroll
        for (int nf = 0; nf < 4; nf++) {
            int col = n0 + wn * 32 + nf * 8 + (lane & 3) * 2;
            atomicAdd(&out[(size_t)tA * NH + col],     acc[mf][nf][0]);
            atomicAdd(&out[(size_t)tA * NH + col + 1], acc[mf][nf][1]);
            atomicAdd(&out[(size_t)tB * NH + col],     acc[mf][nf][2]);
            atomicAdd(&out[(size_t)tB * NH + col + 1], acc[mf][nf][3]);
        }
    }
}

// ---------------- launcher ----------------------------------------------------
extern "C" void kernel_launch(void* const* d_in, const int* in_sizes, int n_in,
                              void* d_out, int out_size) {
    const float* x   = (const float*)d_in[0];
    const int*   idx = (const int*)d_in[1];
    const float* w   = (const float*)d_in[2];
    const float* W1  = (const float*)d_in[3];
    const float* W2  = (const float*)d_in[4];
    float* out = (float*)d_out;

    cudaMemsetAsync(out, 0, (size_t)out_size * sizeof(float));

    k_xc<<<(NT * NH / 8) / 256, 256>>>(x, idx);   // x->fp16 + routing init
    k_r1<<<TKP / 256, 256>>>(idx);
    k_r2<<<1, 256>>>(idx, w);

    dim3 g1(NI / 64, MAXTT);
    k_gemm1<<<g1, 256>>>(W1);

    dim3 g2(NH / 64, MAXTT);
    k_gemm2<<<g2, 256>>>(W2, out);
}

// round 15
// speedup vs baseline: 1.1464x; 1.1464x over previous
#include <cuda_runtime.h>
#include <cuda_fp16.h>
#include <cstdint>

#define NE 32
#define NH 2048
#define NI 768
#define TWO_I 1536
#define NK 4
#define NT 2048
#define TKP 8192
#define PADS 12288
#define MAXTT 128
#define BM 128
#define KC 32
#define ASTR 40
#define BSTR 72

// ---------------- device scratch ---------------------------------------------
__device__ int   g_cnt[NE];
__device__ int   g_cur[NE];
__device__ int   g_tok[PADS];
__device__ float g_w[PADS];
__device__ int   g_is64;
__device__ int   g_tile_e[MAXTT];
__device__ int   g_tile_base[MAXTT];
__device__ __half g_xh[(size_t)NT * NH];
__device__ __half g_i[(size_t)PADS * NI];

// ---------------- helpers -----------------------------------------------------
__device__ __forceinline__ uint32_t smem_u32(const void* p) {
    uint32_t a;
    asm("{ .reg .u64 t; cvta.to.shared.u64 t, %1; cvt.u32.u64 %0, t; }" : "=r"(a) : "l"(p));
    return a;
}
__device__ __forceinline__ void ldm_x4(uint32_t* r, uint32_t addr) {
    asm volatile("ldmatrix.sync.aligned.m8n8.x4.shared.b16 {%0,%1,%2,%3}, [%4];"
        : "=r"(r[0]), "=r"(r[1]), "=r"(r[2]), "=r"(r[3]) : "r"(addr));
}
__device__ __forceinline__ void ldm_x4t(uint32_t* r, uint32_t addr) {
    asm volatile("ldmatrix.sync.aligned.m8n8.x4.trans.shared.b16 {%0,%1,%2,%3}, [%4];"
        : "=r"(r[0]), "=r"(r[1]), "=r"(r[2]), "=r"(r[3]) : "r"(addr));
}
__device__ __forceinline__ void mma_fp16(float* d, const uint32_t* a, const uint32_t* b) {
    asm volatile("mma.sync.aligned.m16n8k16.row.col.f32.f16.f16.f32 "
        "{%0,%1,%2,%3}, {%4,%5,%6,%7}, {%8,%9}, {%0,%1,%2,%3};"
        : "+f"(d[0]), "+f"(d[1]), "+f"(d[2]), "+f"(d[3])
        : "r"(a[0]), "r"(a[1]), "r"(a[2]), "r"(a[3]), "r"(b[0]), "r"(b[1]));
}
__device__ __forceinline__ uint32_t pk2(float f0, float f1) {
    __half2 h = __floats2half2_rn(f0, f1);
    return *reinterpret_cast<uint32_t*>(&h);
}
__device__ __forceinline__ float silu_f(float v) { return v / (1.0f + __expf(-v)); }

__device__ __forceinline__ int fetch_idx(const int* __restrict__ idx, int i, int is64) {
    return is64 ? idx[2 * i] : idx[i];
}
__device__ __forceinline__ int keep_pair(const int* __restrict__ idx, int t, int k,
                                         int e, int is64) {
    for (int k2 = k + 1; k2 < NK; k2++)
        if (fetch_idx(idx, t * NK + k2, is64) == e) return 0;
    return 1;
}

// ---------------- x fp32->fp16 + routing --------------------------------------
__global__ void k_xc(const float* __restrict__ x, const int* __restrict__ idx) {
    int i = blockIdx.x * blockDim.x + threadIdx.x;
    const float4* p = (const float4*)(x + (size_t)i * 8);
    float4 v0 = p[0], v1 = p[1];
    uint4 o;
    o.x = pk2(v0.x, v0.y); o.y = pk2(v0.z, v0.w);
    o.z = pk2(v1.x, v1.y); o.w = pk2(v1.z, v1.w);
    *(uint4*)(g_xh + (size_t)i * 8) = o;
    if (i < PADS) { g_tok[i] = 0; g_w[i] = 0.f; }
    if (i < NE) g_cnt[i] = 0;
    if (i == 0) {
        int ok = 1;
        for (int j = 0; j < 64; j++) if (idx[2 * j + 1] != 0) { ok = 0; break; }
        g_is64 = ok;
    }
}
__global__ void k_r1(const int* __restrict__ idx) {
    int i = blockIdx.x * blockDim.x + threadIdx.x;
    if (i < TKP) {
        int is64 = g_is64;
        int t = i / NK, k = i % NK;
        int e = fetch_idx(idx, i, is64);
        if (keep_pair(idx, t, k, e, is64)) atomicAdd(&g_cnt[e], 1);
    }
}
__global__ void k_r2(const int* __restrict__ idx, const float* __restrict__ wgt) {
    int tid = threadIdx.x;
    if (tid == 0) {
        int pb = 0, tl = 0;
        for (int e = 0; e < NE; e++) {
            g_cur[e] = pb;
            int nt = (g_cnt[e] + BM - 1) / BM;
            for (int j = 0; j < nt; j++) { g_tile_e[tl] = e; g_tile_base[tl] = pb + j * BM; tl++; }
            pb += nt * BM;
        }
        for (int t2 = tl; t2 < MAXTT; t2++) g_tile_e[t2] = -1;
    }
    __syncthreads();
    int is64 = g_is64;
    for (int i = tid; i < TKP; i += blockDim.x) {
        int t = i / NK, k = i % NK;
        int e = fetch_idx(idx, i, is64);
        if (keep_pair(idx, t, k, e, is64)) {
            int pos = atomicAdd(&g_cur[e], 1);
            g_tok[pos] = t; g_w[pos] = wgt[i];
        }
    }
}

// ---------------- GEMM1 (unchanged from R14 — at its L1 floor) ----------------
__global__ __launch_bounds__(256, 2)
void k_gemm1(const float* __restrict__ W1) {
    int tile = blockIdx.y;
    int e = g_tile_e[tile];
    if (e < 0) return;
    int base = g_tile_base[tile];
    int j0 = blockIdx.x * 64;

    __shared__ __align__(16) __half Ab[2][BM * ASTR];
    __shared__ __align__(16) __half Bgb[2][KC * BSTR];
    __shared__ __align__(16) __half Bub[2][KC * BSTR];

    int tid = threadIdx.x, lane = tid & 31, wid = tid >> 5;
    int wm = wid & 3, wn = wid >> 2;

    const float* W = W1 + (size_t)e * NH * TWO_I;

    int arow = tid >> 1, akp = (tid & 1) * 16;
    const __half* xrowh = g_xh + (size_t)g_tok[base + arow] * NH + akp;
    int bkr = tid >> 3, bc = (tid & 7) * 8;
    const float* wbase = W + (size_t)bkr * TWO_I + j0 + bc;
    int oA = arow * ASTR + akp;
    int oB = bkr * BSTR + bc;

    uint32_t sA[2] = { smem_u32(Ab[0]), smem_u32(Ab[1]) };
    uint32_t sBg[2] = { smem_u32(Bgb[0]), smem_u32(Bgb[1]) };
    uint32_t sBu[2] = { smem_u32(Bub[0]), smem_u32(Bub[1]) };

    uint32_t aoff[2], boff[2];
#pragma unroll
    for (int mf = 0; mf < 2; mf++)
        aoff[mf] = (uint32_t)((wm * 32 + mf * 16 + (lane & 15)) * (ASTR * 2) + (lane >> 4) * 16);
#pragma unroll
    for (int nb = 0; nb < 2; nb++)
        boff[nb] = (uint32_t)((lane & 15) * (BSTR * 2) + (wn * 32 + nb * 16 + (lane >> 4) * 8) * 2);

    float accg[2][4][4] = {}, accu[2][4][4] = {};
    const int NC = NH / KC;

    {
        const uint4* pa = (const uint4*)xrowh;
        uint4 va0 = pa[0], va1 = pa[1];
        float4 gg0 = *(const float4*)wbase,        gg1 = *(const float4*)(wbase + 4);
        float4 uu0 = *(const float4*)(wbase + NI), uu1 = *(const float4*)(wbase + NI + 4);
        *(uint4*)&Ab[0][oA]     = va0;
        *(uint4*)&Ab[0][oA + 8] = va1;
        *(uint32_t*)&Bgb[0][oB + 0] = pk2(gg0.x, gg0.y);
        *(uint32_t*)&Bgb[0][oB + 2] = pk2(gg0.z, gg0.w);
        *(uint32_t*)&Bgb[0][oB + 4] = pk2(gg1.x, gg1.y);
        *(uint32_t*)&Bgb[0][oB + 6] = pk2(gg1.z, gg1.w);
        *(uint32_t*)&Bub[0][oB + 0] = pk2(uu0.x, uu0.y);
        *(uint32_t*)&Bub[0][oB + 2] = pk2(uu0.z, uu0.w);
        *(uint32_t*)&Bub[0][oB + 4] = pk2(uu1.x, uu1.y);
        *(uint32_t*)&Bub[0][oB + 6] = pk2(uu1.z, uu1.w);
    }
    __syncthreads();

    for (int c = 0; c < NC; c++) {
        int st = c & 1, ns = st ^ 1;
        bool more = (c + 1 < NC);
        uint4 va0, va1; float4 gg0, gg1, uu0, uu1;
        if (more) {
            int k0 = (c + 1) * KC;
            const uint4* pa = (const uint4*)(xrowh + k0);
            va0 = pa[0]; va1 = pa[1];
            const float* pg = wbase + (size_t)k0 * TWO_I;
            gg0 = *(const float4*)pg;        gg1 = *(const float4*)(pg + 4);
            uu0 = *(const float4*)(pg + NI); uu1 = *(const float4*)(pg + NI + 4);
        }
#pragma unroll
        for (int s = 0; s < 2; s++) {
            uint32_t ah[2][4], bg[2][4], bu[2][4];
            uint32_t as_ = (uint32_t)(s * 32), bs_ = (uint32_t)(s * 16 * BSTR * 2);
            ldm_x4(ah[0], sA[st] + aoff[0] + as_);
            ldm_x4(ah[1], sA[st] + aoff[1] + as_);
            ldm_x4t(bg[0], sBg[st] + boff[0] + bs_);
            ldm_x4t(bg[1], sBg[st] + boff[1] + bs_);
            ldm_x4t(bu[0], sBu[st] + boff[0] + bs_);
            ldm_x4t(bu[1], sBu[st] + boff[1] + bs_);
#pragma unroll
            for (int mf = 0; mf < 2; mf++)
#pragma unroll
                for (int nb = 0; nb < 2; nb++)
#pragma unroll
                    for (int f = 0; f < 2; f++) {
                        mma_fp16(accg[mf][nb * 2 + f], ah[mf], &bg[nb][f * 2]);
                        mma_fp16(accu[mf][nb * 2 + f], ah[mf], &bu[nb][f * 2]);
                    }
        }
        if (more) {
            *(uint4*)&Ab[ns][oA]     = va0;
            *(uint4*)&Ab[ns][oA + 8] = va1;
            *(uint32_t*)&Bgb[ns][oB + 0] = pk2(gg0.x, gg0.y);
            *(uint32_t*)&Bgb[ns][oB + 2] = pk2(gg0.z, gg0.w);
            *(uint32_t*)&Bgb[ns][oB + 4] = pk2(gg1.x, gg1.y);
            *(uint32_t*)&Bgb[ns][oB + 6] = pk2(gg1.z, gg1.w);
            *(uint32_t*)&Bub[ns][oB + 0] = pk2(uu0.x, uu0.y);
            *(uint32_t*)&Bub[ns][oB + 2] = pk2(uu0.z, uu0.w);
            *(uint32_t*)&Bub[ns][oB + 4] = pk2(uu1.x, uu1.y);
            *(uint32_t*)&Bub[ns][oB + 6] = pk2(uu1.z, uu1.w);
        }
        __syncthreads();
    }

#pragma unroll
    for (int mf = 0; mf < 2; mf++) {
        int rA = base + wm * 32 + mf * 16 + (lane >> 2);
        float wa = g_w[rA], wb = g_w[rA + 8];
#pragma unroll
        for (int nf = 0; nf < 4; nf++) {
            int col = j0 + wn * 32 + nf * 8 + (lane & 3) * 2;
            float o0 = silu_f(accg[mf][nf][0]) * accu[mf][nf][0] * wa;
            float o1 = silu_f(accg[mf][nf][1]) * accu[mf][nf][1] * wa;
            float o2 = silu_f(accg[mf][nf][2]) * accu[mf][nf][2] * wb;
            float o3 = silu_f(accg[mf][nf][3]) * accu[mf][nf][3] * wb;
            *(uint32_t*)&g_i[(size_t)rA * NI + col]       = pk2(o0, o1);
            *(uint32_t*)&g_i[(size_t)(rA + 8) * NI + col] = pk2(o2, o3);
        }
    }
}

// ---------------- GEMM2: widened 128x128 tile, float2 atomics -----------------
__global__ __launch_bounds__(256, 2)
void k_gemm2(const float* __restrict__ W2, float* __restrict__ out) {
    int tile = blockIdx.y;
    int e = g_tile_e[tile];
    if (e < 0) return;
    int base = g_tile_base[tile];
    int n0 = blockIdx.x * 128;          // CTA covers 128 output cols

    __shared__ __align__(16) __half Ab[2][BM * ASTR];
    __shared__ __align__(16) __half B0b[2][KC * BSTR];   // cols [n0, n0+64)
    __shared__ __align__(16) __half B1b[2][KC * BSTR];   // cols [n0+64, n0+128)

    int tid = threadIdx.x, lane = tid & 31, wid = tid >> 5;
    int wm = wid & 3, wn = wid >> 2;

    const float* W = W2 + (size_t)e * NI * NH;

    int arow = tid >> 1, akp = (tid & 1) * 16;
    const __half* ip = g_i + (size_t)(base + arow) * NI + akp;
    int bkr = tid >> 3, bc = (tid & 7) * 8;
    const float* wbase = W + (size_t)bkr * NH + n0 + bc;
    int oA = arow * ASTR + akp;
    int oB = bkr * BSTR + bc;

    uint32_t sA[2] = { smem_u32(Ab[0]), smem_u32(Ab[1]) };
    uint32_t sB0[2] = { smem_u32(B0b[0]), smem_u32(B0b[1]) };
    uint32_t sB1[2] = { smem_u32(B1b[0]), smem_u32(B1b[1]) };

    uint32_t aoff[2], boff[2];
#pragma unroll
    for (int mf = 0; mf < 2; mf++)
        aoff[mf] = (uint32_t)((wm * 32 + mf * 16 + (lane & 15)) * (ASTR * 2) + (lane >> 4) * 16);
#pragma unroll
    for (int nb = 0; nb < 2; nb++)
        boff[nb] = (uint32_t)((lane & 15) * (BSTR * 2) + (wn * 32 + nb * 16 + (lane >> 4) * 8) * 2);

    float acc0[2][4][4] = {}, acc1[2][4][4] = {};
    const int NC = NI / KC;

    // ---- prologue: chunk 0 ----
    {
        const uint4* pa = (const uint4*)ip;
        uint4 v0 = pa[0], v1 = pa[1];
        float4 b0 = *(const float4*)wbase,        b1 = *(const float4*)(wbase + 4);
        float4 b2 = *(const float4*)(wbase + 64), b3 = *(const float4*)(wbase + 68);
        *(uint4*)&Ab[0][oA]     = v0;
        *(uint4*)&Ab[0][oA + 8] = v1;
        *(uint32_t*)&B0b[0][oB + 0] = pk2(b0.x, b0.y);
        *(uint32_t*)&B0b[0][oB + 2] = pk2(b0.z, b0.w);
        *(uint32_t*)&B0b[0][oB + 4] = pk2(b1.x, b1.y);
        *(uint32_t*)&B0b[0][oB + 6] = pk2(b1.z, b1.w);
        *(uint32_t*)&B1b[0][oB + 0] = pk2(b2.x, b2.y);
        *(uint32_t*)&B1b[0][oB + 2] = pk2(b2.z, b2.w);
        *(uint32_t*)&B1b[0][oB + 4] = pk2(b3.x, b3.y);
        *(uint32_t*)&B1b[0][oB + 6] = pk2(b3.z, b3.w);
    }
    __syncthreads();

    for (int c = 0; c < NC; c++) {
        int st = c & 1, ns = st ^ 1;
        bool more = (c + 1 < NC);
        uint4 v0, v1; float4 b0, b1, b2, b3;
        if (more) {
            int k0 = (c + 1) * KC;
            const uint4* pa = (const uint4*)(ip + k0);
            v0 = pa[0]; v1 = pa[1];
            const float* pb = wbase + (size_t)k0 * NH;
            b0 = *(const float4*)pb;        b1 = *(const float4*)(pb + 4);
            b2 = *(const float4*)(pb + 64); b3 = *(const float4*)(pb + 68);
        }
#pragma unroll
        for (int s = 0; s < 2; s++) {
            uint32_t ah[2][4], bb0[2][4], bb1[2][4];
            uint32_t as_ = (uint32_t)(s * 32), bs_ = (uint32_t)(s * 16 * BSTR * 2);
            ldm_x4(ah[0], sA[st] + aoff[0] + as_);
            ldm_x4(ah[1], sA[st] + aoff[1] + as_);
            ldm_x4t(bb0[0], sB0[st] + boff[0] + bs_);
            ldm_x4t(bb0[1], sB0[st] + boff[1] + bs_);
            ldm_x4t(bb1[0], sB1[st] + boff[0] + bs_);
            ldm_x4t(bb1[1], sB1[st] + boff[1] + bs_);
#pragma unroll
            for (int mf = 0; mf < 2; mf++)
#pragma unroll
                for (int nb = 0; nb < 2; nb++)
#pragma unroll
                    for (int f = 0; f < 2; f++) {
                        mma_fp16(acc0[mf][nb * 2 + f], ah[mf], &bb0[nb][f * 2]);
                        mma_fp16(acc1[mf][nb * 2 + f], ah[mf], &bb1[nb][f * 2]);
                    }
        }
        if (more) {
            *(uint4*)&Ab[ns][oA]     = v0;
            *(uint4*)&Ab[ns][oA + 8] = v1;
            *(uint32_t*)&B0b[ns][oB + 0] = pk2(b0.x, b0.y);
            *(uint32_t*)&B0b[ns][oB + 2] = pk2(b0.z, b0.w);
            *(uint32_t*)&B0b[ns][oB + 4] = pk2(b1.x, b1.y);
            *(uint32_t*)&B0b[ns][oB + 6] = pk2(b1.z, b1.w);
            *(uint32_t*)&B1b[ns][oB + 0] = pk2(b2.x, b2.y);
            *(uint32_t*)&B1b[ns][oB + 2] = pk2(b2.z, b2.w);
            *(uint32_t*)&B1b[ns][oB + 4] = pk2(b3.x, b3.y);
            *(uint32_t*)&B1b[ns][oB + 6] = pk2(b3.z, b3.w);
        }
        __syncthreads();
    }

    // ---- epilogue: float2 vector atomics (sm_90+) ----
#pragma unroll
    for (int mf = 0; mf < 2; mf++) {
        int rA = base + wm * 32 + mf * 16 + (lane >> 2);
        int tA = g_tok[rA], tB = g_tok[rA + 8];
        float* oa = out + (size_t)tA * NH;
        float* ob = out + (size_t)tB * NH;
#pragma unroll
        for (int nf = 0; nf < 4; nf++) {
            int col = n0 + wn * 32 + nf * 8 + (lane & 3) * 2;
            atomicAdd((float2*)(oa + col),      make_float2(acc0[mf][nf][0], acc0[mf][nf][1]));
            atomicAdd((float2*)(ob + col),      make_float2(acc0[mf][nf][2], acc0[mf][nf][3]));
            atomicAdd((float2*)(oa + col + 64), make_float2(acc1[mf][nf][0], acc1[mf][nf][1]));
            atomicAdd((float2*)(ob + col + 64), make_float2(acc1[mf][nf][2], acc1[mf][nf][3]));
        }
    }
}

// ---------------- launcher ----------------------------------------------------
extern "C" void kernel_launch(void* const* d_in, const int* in_sizes, int n_in,
                              void* d_out, int out_size) {
    const float* x   = (const float*)d_in[0];
    const int*   idx = (const int*)d_in[1];
    const float* w   = (const float*)d_in[2];
    const float* W1  = (const float*)d_in[3];
    const float* W2  = (const float*)d_in[4];
    float* out = (float*)d_out;

    cudaMemsetAsync(out, 0, (size_t)out_size * sizeof(float));

    k_xc<<<(NT * NH / 8) / 256, 256>>>(x, idx);
    k_r1<<<TKP / 256, 256>>>(idx);
    k_r2<<<1, 256>>>(idx, w);

    dim3 g1(NI / 64, MAXTT);
    k_gemm1<<<g1, 256>>>(W1);

    dim3 g2(NH / 128, MAXTT);    // widened: 16 x 128
    k_gemm2<<<g2, 256>>>(W2, out);
}

// round 16
// speedup vs baseline: 1.2555x; 1.0951x over previous
#include <cuda_runtime.h>
#include <cuda_fp16.h>
#include <cstdint>

#define NE 32
#define NH 2048
#define NI 768
#define TWO_I 1536
#define NK 4
#define NT 2048
#define TKP 8192
#define PADS 12288
#define MAXTT 128
#define BM 128
#define KC 32
#define ASTR 40
#define BSTR 72

// ---------------- device scratch ---------------------------------------------
__device__ int   g_cnt[NE];
__device__ int   g_cur[NE];
__device__ int   g_tok[PADS];
__device__ float g_w[PADS];
__device__ int   g_is64;
__device__ int   g_tile_e[MAXTT];
__device__ int   g_tile_base[MAXTT];
__device__ __half g_xh[(size_t)NT * NH];
__device__ __half g_i[(size_t)PADS * NI];

// ---------------- helpers -----------------------------------------------------
__device__ __forceinline__ uint32_t smem_u32(const void* p) {
    uint32_t a;
    asm("{ .reg .u64 t; cvta.to.shared.u64 t, %1; cvt.u32.u64 %0, t; }" : "=r"(a) : "l"(p));
    return a;
}
__device__ __forceinline__ void ldm_x4(uint32_t* r, uint32_t addr) {
    asm volatile("ldmatrix.sync.aligned.m8n8.x4.shared.b16 {%0,%1,%2,%3}, [%4];"
        : "=r"(r[0]), "=r"(r[1]), "=r"(r[2]), "=r"(r[3]) : "r"(addr));
}
__device__ __forceinline__ void ldm_x4t(uint32_t* r, uint32_t addr) {
    asm volatile("ldmatrix.sync.aligned.m8n8.x4.trans.shared.b16 {%0,%1,%2,%3}, [%4];"
        : "=r"(r[0]), "=r"(r[1]), "=r"(r[2]), "=r"(r[3]) : "r"(addr));
}
__device__ __forceinline__ void mma_fp16(float* d, const uint32_t* a, const uint32_t* b) {
    asm volatile("mma.sync.aligned.m16n8k16.row.col.f32.f16.f16.f32 "
        "{%0,%1,%2,%3}, {%4,%5,%6,%7}, {%8,%9}, {%0,%1,%2,%3};"
        : "+f"(d[0]), "+f"(d[1]), "+f"(d[2]), "+f"(d[3])
        : "r"(a[0]), "r"(a[1]), "r"(a[2]), "r"(a[3]), "r"(b[0]), "r"(b[1]));
}
__device__ __forceinline__ uint32_t pk2(float f0, float f1) {
    __half2 h = __floats2half2_rn(f0, f1);
    return *reinterpret_cast<uint32_t*>(&h);
}
__device__ __forceinline__ float silu_f(float v) { return v / (1.0f + __expf(-v)); }

__device__ __forceinline__ int fetch_idx(const int* __restrict__ idx, int i, int is64) {
    return is64 ? idx[2 * i] : idx[i];
}
__device__ __forceinline__ int keep_pair(const int* __restrict__ idx, int t, int k,
                                         int e, int is64) {
    for (int k2 = k + 1; k2 < NK; k2++)
        if (fetch_idx(idx, t * NK + k2, is64) == e) return 0;
    return 1;
}

// ---------------- x fp32->fp16 + out zeroing + routing init --------------------
__global__ void k_xc(const float* __restrict__ x, const int* __restrict__ idx,
                     float* __restrict__ out) {
    int i = blockIdx.x * blockDim.x + threadIdx.x;
    const float4* p = (const float4*)(x + (size_t)i * 8);
    float4 v0 = p[0], v1 = p[1];
    uint4 o;
    o.x = pk2(v0.x, v0.y); o.y = pk2(v0.z, v0.w);
    o.z = pk2(v1.x, v1.y); o.w = pk2(v1.z, v1.w);
    *(uint4*)(g_xh + (size_t)i * 8) = o;
    float4 z = make_float4(0.f, 0.f, 0.f, 0.f);
    float4* po = (float4*)(out + (size_t)i * 8);
    po[0] = z; po[1] = z;
    if (i < PADS) { g_tok[i] = 0; g_w[i] = 0.f; }
    if (i < NE) g_cnt[i] = 0;
    if (i == 0) {
        int ok = 1;
        for (int j = 0; j < 64; j++) if (idx[2 * j + 1] != 0) { ok = 0; break; }
        g_is64 = ok;
    }
}
__global__ void k_r1(const int* __restrict__ idx) {
    int i = blockIdx.x * blockDim.x + threadIdx.x;
    if (i < TKP) {
        int is64 = g_is64;
        int t = i / NK, k = i % NK;
        int e = fetch_idx(idx, i, is64);
        if (keep_pair(idx, t, k, e, is64)) atomicAdd(&g_cnt[e], 1);
    }
}
__global__ void k_r2(const int* __restrict__ idx, const float* __restrict__ wgt) {
    int tid = threadIdx.x;
    if (tid == 0) {
        int pb = 0, tl = 0;
        for (int e = 0; e < NE; e++) {
            g_cur[e] = pb;
            int nt = (g_cnt[e] + BM - 1) / BM;
            for (int j = 0; j < nt; j++) { g_tile_e[tl] = e; g_tile_base[tl] = pb + j * BM; tl++; }
            pb += nt * BM;
        }
        for (int t2 = tl; t2 < MAXTT; t2++) g_tile_e[t2] = -1;
    }
    __syncthreads();
    int is64 = g_is64;
    for (int i = tid; i < TKP; i += blockDim.x) {
        int t = i / NK, k = i % NK;
        int e = fetch_idx(idx, i, is64);
        if (keep_pair(idx, t, k, e, is64)) {
            int pos = atomicAdd(&g_cur[e], 1);
            g_tok[pos] = t; g_w[pos] = wgt[i];
        }
    }
}

// ---------------- GEMM1: STS-early pipelined loop ------------------------------
__global__ __launch_bounds__(256, 2)
void k_gemm1(const float* __restrict__ W1) {
    int tile = blockIdx.y;
    int e = g_tile_e[tile];
    if (e < 0) return;
    int base = g_tile_base[tile];
    int j0 = blockIdx.x * 64;

    __shared__ __align__(16) __half Ab[2][BM * ASTR];
    __shared__ __align__(16) __half Bgb[2][KC * BSTR];
    __shared__ __align__(16) __half Bub[2][KC * BSTR];

    int tid = threadIdx.x, lane = tid & 31, wid = tid >> 5;
    int wm = wid & 3, wn = wid >> 2;

    const float* W = W1 + (size_t)e * NH * TWO_I;

    int arow = tid >> 1, akp = (tid & 1) * 16;
    const __half* xrowh = g_xh + (size_t)g_tok[base + arow] * NH + akp;
    int bkr = tid >> 3, bc = (tid & 7) * 8;
    const float* wbase = W + (size_t)bkr * TWO_I + j0 + bc;
    int oA = arow * ASTR + akp;
    int oB = bkr * BSTR + bc;

    uint32_t sA[2] = { smem_u32(Ab[0]), smem_u32(Ab[1]) };
    uint32_t sBg[2] = { smem_u32(Bgb[0]), smem_u32(Bgb[1]) };
    uint32_t sBu[2] = { smem_u32(Bub[0]), smem_u32(Bub[1]) };

    uint32_t aoff[2], boff[2];
#pragma unroll
    for (int mf = 0; mf < 2; mf++)
        aoff[mf] = (uint32_t)((wm * 32 + mf * 16 + (lane & 15)) * (ASTR * 2) + (lane >> 4) * 16);
#pragma unroll
    for (int nb = 0; nb < 2; nb++)
        boff[nb] = (uint32_t)((lane & 15) * (BSTR * 2) + (wn * 32 + nb * 16 + (lane >> 4) * 8) * 2);

    float accg[2][4][4] = {}, accu[2][4][4] = {};
    const int NC = NH / KC;

    // ---- prologue: chunk 0 -> buf0; LDG chunk 1 -> regs ----
    uint4 va0, va1; float4 gg0, gg1, uu0, uu1;
    {
        const uint4* pa = (const uint4*)xrowh;
        va0 = pa[0]; va1 = pa[1];
        gg0 = *(const float4*)wbase;        gg1 = *(const float4*)(wbase + 4);
        uu0 = *(const float4*)(wbase + NI); uu1 = *(const float4*)(wbase + NI + 4);
        *(uint4*)&Ab[0][oA]     = va0;
        *(uint4*)&Ab[0][oA + 8] = va1;
        *(uint32_t*)&Bgb[0][oB + 0] = pk2(gg0.x, gg0.y);
        *(uint32_t*)&Bgb[0][oB + 2] = pk2(gg0.z, gg0.w);
        *(uint32_t*)&Bgb[0][oB + 4] = pk2(gg1.x, gg1.y);
        *(uint32_t*)&Bgb[0][oB + 6] = pk2(gg1.z, gg1.w);
        *(uint32_t*)&Bub[0][oB + 0] = pk2(uu0.x, uu0.y);
        *(uint32_t*)&Bub[0][oB + 2] = pk2(uu0.z, uu0.w);
        *(uint32_t*)&Bub[0][oB + 4] = pk2(uu1.x, uu1.y);
        *(uint32_t*)&Bub[0][oB + 6] = pk2(uu1.z, uu1.w);
        const uint4* pa1 = (const uint4*)(xrowh + KC);
        va0 = pa1[0]; va1 = pa1[1];
        const float* pg = wbase + (size_t)KC * TWO_I;
        gg0 = *(const float4*)pg;        gg1 = *(const float4*)(pg + 4);
        uu0 = *(const float4*)(pg + NI); uu1 = *(const float4*)(pg + NI + 4);
    }
    __syncthreads();

    for (int c = 0; c < NC; c++) {
        int st = c & 1, ns = st ^ 1;
        // ---- 1) STS chunk c+1 (regs loaded LAST iteration -> no LDG wait) ----
        if (c + 1 < NC) {
            *(uint4*)&Ab[ns][oA]     = va0;
            *(uint4*)&Ab[ns][oA + 8] = va1;
            *(uint32_t*)&Bgb[ns][oB + 0] = pk2(gg0.x, gg0.y);
            *(uint32_t*)&Bgb[ns][oB + 2] = pk2(gg0.z, gg0.w);
            *(uint32_t*)&Bgb[ns][oB + 4] = pk2(gg1.x, gg1.y);
            *(uint32_t*)&Bgb[ns][oB + 6] = pk2(gg1.z, gg1.w);
            *(uint32_t*)&Bub[ns][oB + 0] = pk2(uu0.x, uu0.y);
            *(uint32_t*)&Bub[ns][oB + 2] = pk2(uu0.z, uu0.w);
            *(uint32_t*)&Bub[ns][oB + 4] = pk2(uu1.x, uu1.y);
            *(uint32_t*)&Bub[ns][oB + 6] = pk2(uu1.z, uu1.w);
        }
        // ---- 2) LDG chunk c+2 -> regs (2 iterations of latency cover) ----
        if (c + 2 < NC) {
            int k0 = (c + 2) * KC;
            const uint4* pa = (const uint4*)(xrowh + k0);
            va0 = pa[0]; va1 = pa[1];
            const float* pg = wbase + (size_t)k0 * TWO_I;
            gg0 = *(const float4*)pg;        gg1 = *(const float4*)(pg + 4);
            uu0 = *(const float4*)(pg + NI); uu1 = *(const float4*)(pg + NI + 4);
        }
        // ---- 3) MMA on chunk c from buf[st] ----
#pragma unroll
        for (int s = 0; s < 2; s++) {
            uint32_t ah[2][4], bg[2][4], bu[2][4];
            uint32_t as_ = (uint32_t)(s * 32), bs_ = (uint32_t)(s * 16 * BSTR * 2);
            ldm_x4(ah[0], sA[st] + aoff[0] + as_);
            ldm_x4(ah[1], sA[st] + aoff[1] + as_);
            ldm_x4t(bg[0], sBg[st] + boff[0] + bs_);
            ldm_x4t(bg[1], sBg[st] + boff[1] + bs_);
            ldm_x4t(bu[0], sBu[st] + boff[0] + bs_);
            ldm_x4t(bu[1], sBu[st] + boff[1] + bs_);
#pragma unroll
            for (int mf = 0; mf < 2; mf++)
#pragma unroll
                for (int nb = 0; nb < 2; nb++)
#pragma unroll
                    for (int f = 0; f < 2; f++) {
                        mma_fp16(accg[mf][nb * 2 + f], ah[mf], &bg[nb][f * 2]);
                        mma_fp16(accu[mf][nb * 2 + f], ah[mf], &bu[nb][f * 2]);
                    }
        }
        __syncthreads();
    }

    // ---- epilogue ----
#pragma unroll
    for (int mf = 0; mf < 2; mf++) {
        int rA = base + wm * 32 + mf * 16 + (lane >> 2);
        float wa = g_w[rA], wb = g_w[rA + 8];
#pragma unroll
        for (int nf = 0; nf < 4; nf++) {
            int col = j0 + wn * 32 + nf * 8 + (lane & 3) * 2;
            float o0 = silu_f(accg[mf][nf][0]) * accu[mf][nf][0] * wa;
            float o1 = silu_f(accg[mf][nf][1]) * accu[mf][nf][1] * wa;
            float o2 = silu_f(accg[mf][nf][2]) * accu[mf][nf][2] * wb;
            float o3 = silu_f(accg[mf][nf][3]) * accu[mf][nf][3] * wb;
            *(uint32_t*)&g_i[(size_t)rA * NI + col]       = pk2(o0, o1);
            *(uint32_t*)&g_i[(size_t)(rA + 8) * NI + col] = pk2(o2, o3);
        }
    }
}

// ---------------- GEMM2: 128x128 tile, STS-early pipeline, float2 atomics -----
__global__ __launch_bounds__(256, 2)
void k_gemm2(const float* __restrict__ W2, float* __restrict__ out) {
    int tile = blockIdx.y;
    int e = g_tile_e[tile];
    if (e < 0) return;
    int base = g_tile_base[tile];
    int n0 = blockIdx.x * 128;

    __shared__ __align__(16) __half Ab[2][BM * ASTR];
    __shared__ __align__(16) __half B0b[2][KC * BSTR];
    __shared__ __align__(16) __half B1b[2][KC * BSTR];

    int tid = threadIdx.x, lane = tid & 31, wid = tid >> 5;
    int wm = wid & 3, wn = wid >> 2;

    const float* W = W2 + (size_t)e * NI * NH;

    int arow = tid >> 1, akp = (tid & 1) * 16;
    const __half* ip = g_i + (size_t)(base + arow) * NI + akp;
    int bkr = tid >> 3, bc = (tid & 7) * 8;
    const float* wbase = W + (size_t)bkr * NH + n0 + bc;
    int oA = arow * ASTR + akp;
    int oB = bkr * BSTR + bc;

    uint32_t sA[2] = { smem_u32(Ab[0]), smem_u32(Ab[1]) };
    uint32_t sB0[2] = { smem_u32(B0b[0]), smem_u32(B0b[1]) };
    uint32_t sB1[2] = { smem_u32(B1b[0]), smem_u32(B1b[1]) };

    uint32_t aoff[2], boff[2];
#pragma unroll
    for (int mf = 0; mf < 2; mf++)
        aoff[mf] = (uint32_t)((wm * 32 + mf * 16 + (lane & 15)) * (ASTR * 2) + (lane >> 4) * 16);
#pragma unroll
    for (int nb = 0; nb < 2; nb++)
        boff[nb] = (uint32_t)((lane & 15) * (BSTR * 2) + (wn * 32 + nb * 16 + (lane >> 4) * 8) * 2);

    float acc0[2][4][4] = {}, acc1[2][4][4] = {};
    const int NC = NI / KC;

    uint4 v0, v1; float4 b0, b1, b2, b3;
    {
        const uint4* pa = (const uint4*)ip;
        v0 = pa[0]; v1 = pa[1];
        b0 = *(const float4*)wbase;        b1 = *(const float4*)(wbase + 4);
        b2 = *(const float4*)(wbase + 64); b3 = *(const float4*)(wbase + 68);
        *(uint4*)&Ab[0][oA]     = v0;
        *(uint4*)&Ab[0][oA + 8] = v1;
        *(uint32_t*)&B0b[0][oB + 0] = pk2(b0.x, b0.y);
        *(uint32_t*)&B0b[0][oB + 2] = pk2(b0.z, b0.w);
        *(uint32_t*)&B0b[0][oB + 4] = pk2(b1.x, b1.y);
        *(uint32_t*)&B0b[0][oB + 6] = pk2(b1.z, b1.w);
        *(uint32_t*)&B1b[0][oB + 0] = pk2(b2.x, b2.y);
        *(uint32_t*)&B1b[0][oB + 2] = pk2(b2.z, b2.w);
        *(uint32_t*)&B1b[0][oB + 4] = pk2(b3.x, b3.y);
        *(uint32_t*)&B1b[0][oB + 6] = pk2(b3.z, b3.w);
        const uint4* pa1 = (const uint4*)(ip + KC);
        v0 = pa1[0]; v1 = pa1[1];
        const float* pb = wbase + (size_t)KC * NH;
        b0 = *(const float4*)pb;        b1 = *(const float4*)(pb + 4);
        b2 = *(const float4*)(pb + 64); b3 = *(const float4*)(pb + 68);
    }
    __syncthreads();

    for (int c = 0; c < NC; c++) {
        int st = c & 1, ns = st ^ 1;
        if (c + 1 < NC) {
            *(uint4*)&Ab[ns][oA]     = v0;
            *(uint4*)&Ab[ns][oA + 8] = v1;
            *(uint32_t*)&B0b[ns][oB + 0] = pk2(b0.x, b0.y);
            *(uint32_t*)&B0b[ns][oB + 2] = pk2(b0.z, b0.w);
            *(uint32_t*)&B0b[ns][oB + 4] = pk2(b1.x, b1.y);
            *(uint32_t*)&B0b[ns][oB + 6] = pk2(b1.z, b1.w);
            *(uint32_t*)&B1b[ns][oB + 0] = pk2(b2.x, b2.y);
            *(uint32_t*)&B1b[ns][oB + 2] = pk2(b2.z, b2.w);
            *(uint32_t*)&B1b[ns][oB + 4] = pk2(b3.x, b3.y);
            *(uint32_t*)&B1b[ns][oB + 6] = pk2(b3.z, b3.w);
        }
        if (c + 2 < NC) {
            int k0 = (c + 2) * KC;
            const uint4* pa = (const uint4*)(ip + k0);
            v0 = pa[0]; v1 = pa[1];
            const float* pb = wbase + (size_t)k0 * NH;
            b0 = *(const float4*)pb;        b1 = *(const float4*)(pb + 4);
            b2 = *(const float4*)(pb + 64); b3 = *(const float4*)(pb + 68);
        }
#pragma unroll
        for (int s = 0; s < 2; s++) {
            uint32_t ah[2][4], bb0[2][4], bb1[2][4];
            uint32_t as_ = (uint32_t)(s * 32), bs_ = (uint32_t)(s * 16 * BSTR * 2);
            ldm_x4(ah[0], sA[st] + aoff[0] + as_);
            ldm_x4(ah[1], sA[st] + aoff[1] + as_);
            ldm_x4t(bb0[0], sB0[st] + boff[0] + bs_);
            ldm_x4t(bb0[1], sB0[st] + boff[1] + bs_);
            ldm_x4t(bb1[0], sB1[st] + boff[0] + bs_);
            ldm_x4t(bb1[1], sB1[st] + boff[1] + bs_);
#pragma unroll
            for (int mf = 0; mf < 2; mf++)
#pragma unroll
                for (int nb = 0; nb < 2; nb++)
#pragma unroll
                    for (int f = 0; f < 2; f++) {
                        mma_fp16(acc0[mf][nb * 2 + f], ah[mf], &bb0[nb][f * 2]);
                        mma_fp16(acc1[mf][nb * 2 + f], ah[mf], &bb1[nb][f * 2]);
                    }
        }
        __syncthreads();
    }

#pragma unroll
    for (int mf = 0; mf < 2; mf++) {
        int rA = base + wm * 32 + mf * 16 + (lane >> 2);
        int tA = g_tok[rA], tB = g_tok[rA + 8];
        float* oa = out + (size_t)tA * NH;
        float* ob = out + (size_t)tB * NH;
#pragma unroll
        for (int nf = 0; nf < 4; nf++) {
            int col = n0 + wn * 32 + nf * 8 + (lane & 3) * 2;
            atomicAdd((float2*)(oa + col),      make_float2(acc0[mf][nf][0], acc0[mf][nf][1]));
            atomicAdd((float2*)(ob + col),      make_float2(acc0[mf][nf][2], acc0[mf][nf][3]));
            atomicAdd((float2*)(oa + col + 64), make_float2(acc1[mf][nf][0], acc1[mf][nf][1]));
            atomicAdd((float2*)(ob + col + 64), make_float2(acc1[mf][nf][2], acc1[mf][nf][3]));
        }
    }
}

// ---------------- launcher ----------------------------------------------------
extern "C" void kernel_launch(void* const* d_in, const int* in_sizes, int n_in,
                              void* d_out, int out_size) {
    const float* x   = (const float*)d_in[0];
    const int*   idx = (const int*)d_in[1];
    const float* w   = (const float*)d_in[2];
    const float* W1  = (const float*)d_in[3];
    const float* W2  = (const float*)d_in[4];
    float* out = (float*)d_out;

    k_xc<<<(NT * NH / 8) / 256, 256>>>(x, idx, out);   // x->fp16 + zero out + init
    k_r1<<<TKP / 256, 256>>>(idx);
    k_r2<<<1, 1024>>>(idx, w);

    dim3 g1(NI / 64, MAXTT);
    k_gemm1<<<g1, 256>>>(W1);

    dim3 g2(NH / 128, MAXTT);
    k_gemm2<<<g2, 256>>>(W2, out);
}

// round 17
// speedup vs baseline: 1.3999x; 1.1150x over previous
#include <cuda_runtime.h>
#include <cuda_fp16.h>
#include <cstdint>

#define NE 32
#define NH 2048
#define NI 768
#define TWO_I 1536
#define NK 4
#define NT 2048
#define TKP 8192
#define PADS 12288
#define MAXTT 128
#define BM 128
#define KC 32
#define ASTR 40
#define BSTR 72

// ---------------- device scratch ---------------------------------------------
__device__ int   g_cnt[NE];
__device__ int   g_cur[NE];
__device__ int   g_tok[PADS];
__device__ float g_w[PADS];
__device__ int   g_is64;
__device__ int   g_tile_e[MAXTT];
__device__ int   g_tile_base[MAXTT];
__device__ __half g_xh[(size_t)NT * NH];
__device__ __half g_i[(size_t)PADS * NI];

// ---------------- helpers -----------------------------------------------------
__device__ __forceinline__ uint32_t smem_u32(const void* p) {
    uint32_t a;
    asm("{ .reg .u64 t; cvta.to.shared.u64 t, %1; cvt.u32.u64 %0, t; }" : "=r"(a) : "l"(p));
    return a;
}
#define CPA16(dst, src) asm volatile("cp.async.cg.shared.global [%0], [%1], 16;" :: "r"(dst), "l"(src))
#define CPA_COMMIT()    asm volatile("cp.async.commit_group;" ::: "memory")
#define CPA_WAIT0()     asm volatile("cp.async.wait_group 0;" ::: "memory")

__device__ __forceinline__ void ldm_x4(uint32_t* r, uint32_t addr) {
    asm volatile("ldmatrix.sync.aligned.m8n8.x4.shared.b16 {%0,%1,%2,%3}, [%4];"
        : "=r"(r[0]), "=r"(r[1]), "=r"(r[2]), "=r"(r[3]) : "r"(addr));
}
__device__ __forceinline__ void ldm_x4t(uint32_t* r, uint32_t addr) {
    asm volatile("ldmatrix.sync.aligned.m8n8.x4.trans.shared.b16 {%0,%1,%2,%3}, [%4];"
        : "=r"(r[0]), "=r"(r[1]), "=r"(r[2]), "=r"(r[3]) : "r"(addr));
}
__device__ __forceinline__ void mma_fp16(float* d, const uint32_t* a, const uint32_t* b) {
    asm volatile("mma.sync.aligned.m16n8k16.row.col.f32.f16.f16.f32 "
        "{%0,%1,%2,%3}, {%4,%5,%6,%7}, {%8,%9}, {%0,%1,%2,%3};"
        : "+f"(d[0]), "+f"(d[1]), "+f"(d[2]), "+f"(d[3])
        : "r"(a[0]), "r"(a[1]), "r"(a[2]), "r"(a[3]), "r"(b[0]), "r"(b[1]));
}
__device__ __forceinline__ uint32_t pk2(float f0, float f1) {
    __half2 h = __floats2half2_rn(f0, f1);
    return *reinterpret_cast<uint32_t*>(&h);
}
__device__ __forceinline__ float silu_f(float v) { return v / (1.0f + __expf(-v)); }

__device__ __forceinline__ int fetch_idx(const int* __restrict__ idx, int i, int is64) {
    return is64 ? idx[2 * i] : idx[i];
}
__device__ __forceinline__ int keep_pair(const int* __restrict__ idx, int t, int k,
                                         int e, int is64) {
    for (int k2 = k + 1; k2 < NK; k2++)
        if (fetch_idx(idx, t * NK + k2, is64) == e) return 0;
    return 1;
}

// ---------------- x fp32->fp16 + out zeroing + routing init --------------------
__global__ void k_xc(const float* __restrict__ x, const int* __restrict__ idx,
                     float* __restrict__ out) {
    int i = blockIdx.x * blockDim.x + threadIdx.x;
    const float4* p = (const float4*)(x + (size_t)i * 8);
    float4 v0 = p[0], v1 = p[1];
    uint4 o;
    o.x = pk2(v0.x, v0.y); o.y = pk2(v0.z, v0.w);
    o.z = pk2(v1.x, v1.y); o.w = pk2(v1.z, v1.w);
    *(uint4*)(g_xh + (size_t)i * 8) = o;
    float4 z = make_float4(0.f, 0.f, 0.f, 0.f);
    float4* po = (float4*)(out + (size_t)i * 8);
    po[0] = z; po[1] = z;
    if (i < PADS) { g_tok[i] = 0; g_w[i] = 0.f; }
    if (i < NE) g_cnt[i] = 0;
    if (i == 0) {
        int ok = 1;
        for (int j = 0; j < 64; j++) if (idx[2 * j + 1] != 0) { ok = 0; break; }
        g_is64 = ok;
    }
}
__global__ void k_r1(const int* __restrict__ idx) {
    int i = blockIdx.x * blockDim.x + threadIdx.x;
    if (i < TKP) {
        int is64 = g_is64;
        int t = i / NK, k = i % NK;
        int e = fetch_idx(idx, i, is64);
        if (keep_pair(idx, t, k, e, is64)) atomicAdd(&g_cnt[e], 1);
    }
}
__global__ void k_r2(const int* __restrict__ idx, const float* __restrict__ wgt) {
    int tid = threadIdx.x;
    if (tid == 0) {
        int pb = 0, tl = 0;
        for (int e = 0; e < NE; e++) {
            g_cur[e] = pb;
            int nt = (g_cnt[e] + BM - 1) / BM;
            for (int j = 0; j < nt; j++) { g_tile_e[tl] = e; g_tile_base[tl] = pb + j * BM; tl++; }
            pb += nt * BM;
        }
        for (int t2 = tl; t2 < MAXTT; t2++) g_tile_e[t2] = -1;
    }
    __syncthreads();
    int is64 = g_is64;
    for (int i = tid; i < TKP; i += blockDim.x) {
        int t = i / NK, k = i % NK;
        int e = fetch_idx(idx, i, is64);
        if (keep_pair(idx, t, k, e, is64)) {
            int pos = atomicAdd(&g_cur[e], 1);
            g_tok[pos] = t; g_w[pos] = wgt[i];
        }
    }
}

// ---------------- GEMM1: cp.async A, STS-early B -------------------------------
__global__ __launch_bounds__(256, 2)
void k_gemm1(const float* __restrict__ W1) {
    int tile = blockIdx.y;
    int e = g_tile_e[tile];
    if (e < 0) return;
    int base = g_tile_base[tile];
    int j0 = blockIdx.x * 64;

    __shared__ __align__(16) __half Ab[2][BM * ASTR];
    __shared__ __align__(16) __half Bgb[2][KC * BSTR];
    __shared__ __align__(16) __half Bub[2][KC * BSTR];

    int tid = threadIdx.x, lane = tid & 31, wid = tid >> 5;
    int wm = wid & 3, wn = wid >> 2;

    const float* W = W1 + (size_t)e * NH * TWO_I;

    int arow = tid >> 1, akp = (tid & 1) * 16;
    const __half* xrowh = g_xh + (size_t)g_tok[base + arow] * NH + akp;
    int bkr = tid >> 3, bc = (tid & 7) * 8;
    const float* wbase = W + (size_t)bkr * TWO_I + j0 + bc;
    int oA = arow * ASTR + akp;
    int oB = bkr * BSTR + bc;

    uint32_t sA[2] = { smem_u32(Ab[0]), smem_u32(Ab[1]) };
    uint32_t sBg[2] = { smem_u32(Bgb[0]), smem_u32(Bgb[1]) };
    uint32_t sBu[2] = { smem_u32(Bub[0]), smem_u32(Bub[1]) };
    uint32_t dA[2] = { sA[0] + (uint32_t)oA * 2, sA[1] + (uint32_t)oA * 2 };

    uint32_t aoff[2], boff[2];
#pragma unroll
    for (int mf = 0; mf < 2; mf++)
        aoff[mf] = (uint32_t)((wm * 32 + mf * 16 + (lane & 15)) * (ASTR * 2) + (lane >> 4) * 16);
#pragma unroll
    for (int nb = 0; nb < 2; nb++)
        boff[nb] = (uint32_t)((lane & 15) * (BSTR * 2) + (wn * 32 + nb * 16 + (lane >> 4) * 8) * 2);

    float accg[2][4][4] = {}, accu[2][4][4] = {};
    const int NC = NH / KC;

    // ---- prologue: A(0) via cp.async; B(0) convert->buf0; B(1) -> regs ----
    float4 gg0, gg1, uu0, uu1;
    {
        CPA16(dA[0],      xrowh);
        CPA16(dA[0] + 16, xrowh + 8);
        CPA_COMMIT();
        gg0 = *(const float4*)wbase;        gg1 = *(const float4*)(wbase + 4);
        uu0 = *(const float4*)(wbase + NI); uu1 = *(const float4*)(wbase + NI + 4);
        *(uint32_t*)&Bgb[0][oB + 0] = pk2(gg0.x, gg0.y);
        *(uint32_t*)&Bgb[0][oB + 2] = pk2(gg0.z, gg0.w);
        *(uint32_t*)&Bgb[0][oB + 4] = pk2(gg1.x, gg1.y);
        *(uint32_t*)&Bgb[0][oB + 6] = pk2(gg1.z, gg1.w);
        *(uint32_t*)&Bub[0][oB + 0] = pk2(uu0.x, uu0.y);
        *(uint32_t*)&Bub[0][oB + 2] = pk2(uu0.z, uu0.w);
        *(uint32_t*)&Bub[0][oB + 4] = pk2(uu1.x, uu1.y);
        *(uint32_t*)&Bub[0][oB + 6] = pk2(uu1.z, uu1.w);
        const float* pg = wbase + (size_t)KC * TWO_I;
        gg0 = *(const float4*)pg;        gg1 = *(const float4*)(pg + 4);
        uu0 = *(const float4*)(pg + NI); uu1 = *(const float4*)(pg + NI + 4);
    }
    CPA_WAIT0();
    __syncthreads();

    for (int c = 0; c < NC; c++) {
        int st = c & 1, ns = st ^ 1;
        // ---- 1) cp.async A(c+1) -> buf[ns]; STS B(c+1) from regs ----
        if (c + 1 < NC) {
            const __half* pa = xrowh + (c + 1) * KC;
            CPA16(dA[ns],      pa);
            CPA16(dA[ns] + 16, pa + 8);
            *(uint32_t*)&Bgb[ns][oB + 0] = pk2(gg0.x, gg0.y);
            *(uint32_t*)&Bgb[ns][oB + 2] = pk2(gg0.z, gg0.w);
            *(uint32_t*)&Bgb[ns][oB + 4] = pk2(gg1.x, gg1.y);
            *(uint32_t*)&Bgb[ns][oB + 6] = pk2(gg1.z, gg1.w);
            *(uint32_t*)&Bub[ns][oB + 0] = pk2(uu0.x, uu0.y);
            *(uint32_t*)&Bub[ns][oB + 2] = pk2(uu0.z, uu0.w);
            *(uint32_t*)&Bub[ns][oB + 4] = pk2(uu1.x, uu1.y);
            *(uint32_t*)&Bub[ns][oB + 6] = pk2(uu1.z, uu1.w);
        }
        CPA_COMMIT();
        // ---- 2) LDG B(c+2) -> regs ----
        if (c + 2 < NC) {
            const float* pg = wbase + (size_t)((c + 2) * KC) * TWO_I;
            gg0 = *(const float4*)pg;        gg1 = *(const float4*)(pg + 4);
            uu0 = *(const float4*)(pg + NI); uu1 = *(const float4*)(pg + NI + 4);
        }
        // ---- 3) MMA on chunk c ----
#pragma unroll
        for (int s = 0; s < 2; s++) {
            uint32_t ah[2][4], bg[2][4], bu[2][4];
            uint32_t as_ = (uint32_t)(s * 32), bs_ = (uint32_t)(s * 16 * BSTR * 2);
            ldm_x4(ah[0], sA[st] + aoff[0] + as_);
            ldm_x4(ah[1], sA[st] + aoff[1] + as_);
            ldm_x4t(bg[0], sBg[st] + boff[0] + bs_);
            ldm_x4t(bg[1], sBg[st] + boff[1] + bs_);
            ldm_x4t(bu[0], sBu[st] + boff[0] + bs_);
            ldm_x4t(bu[1], sBu[st] + boff[1] + bs_);
#pragma unroll
            for (int mf = 0; mf < 2; mf++)
#pragma unroll
                for (int nb = 0; nb < 2; nb++)
#pragma unroll
                    for (int f = 0; f < 2; f++) {
                        mma_fp16(accg[mf][nb * 2 + f], ah[mf], &bg[nb][f * 2]);
                        mma_fp16(accu[mf][nb * 2 + f], ah[mf], &bu[nb][f * 2]);
                    }
        }
        CPA_WAIT0();
        __syncthreads();
    }

    // ---- epilogue ----
#pragma unroll
    for (int mf = 0; mf < 2; mf++) {
        int rA = base + wm * 32 + mf * 16 + (lane >> 2);
        float wa = g_w[rA], wb = g_w[rA + 8];
#pragma unroll
        for (int nf = 0; nf < 4; nf++) {
            int col = j0 + wn * 32 + nf * 8 + (lane & 3) * 2;
            float o0 = silu_f(accg[mf][nf][0]) * accu[mf][nf][0] * wa;
            float o1 = silu_f(accg[mf][nf][1]) * accu[mf][nf][1] * wa;
            float o2 = silu_f(accg[mf][nf][2]) * accu[mf][nf][2] * wb;
            float o3 = silu_f(accg[mf][nf][3]) * accu[mf][nf][3] * wb;
            *(uint32_t*)&g_i[(size_t)rA * NI + col]       = pk2(o0, o1);
            *(uint32_t*)&g_i[(size_t)(rA + 8) * NI + col] = pk2(o2, o3);
        }
    }
}

// ---------------- GEMM2: 128x128, cp.async A, float2 atomics -------------------
__global__ __launch_bounds__(256, 2)
void k_gemm2(const float* __restrict__ W2, float* __restrict__ out) {
    int tile = blockIdx.y;
    int e = g_tile_e[tile];
    if (e < 0) return;
    int base = g_tile_base[tile];
    int n0 = blockIdx.x * 128;

    __shared__ __align__(16) __half Ab[2][BM * ASTR];
    __shared__ __align__(16) __half B0b[2][KC * BSTR];
    __shared__ __align__(16) __half B1b[2][KC * BSTR];

    int tid = threadIdx.x, lane = tid & 31, wid = tid >> 5;
    int wm = wid & 3, wn = wid >> 2;

    const float* W = W2 + (size_t)e * NI * NH;

    int arow = tid >> 1, akp = (tid & 1) * 16;
    const __half* ip = g_i + (size_t)(base + arow) * NI + akp;
    int bkr = tid >> 3, bc = (tid & 7) * 8;
    const float* wbase = W + (size_t)bkr * NH + n0 + bc;
    int oA = arow * ASTR + akp;
    int oB = bkr * BSTR + bc;

    uint32_t sA[2] = { smem_u32(Ab[0]), smem_u32(Ab[1]) };
    uint32_t sB0[2] = { smem_u32(B0b[0]), smem_u32(B0b[1]) };
    uint32_t sB1[2] = { smem_u32(B1b[0]), smem_u32(B1b[1]) };
    uint32_t dA[2] = { sA[0] + (uint32_t)oA * 2, sA[1] + (uint32_t)oA * 2 };

    uint32_t aoff[2], boff[2];
#pragma unroll
    for (int mf = 0; mf < 2; mf++)
        aoff[mf] = (uint32_t)((wm * 32 + mf * 16 + (lane & 15)) * (ASTR * 2) + (lane >> 4) * 16);
#pragma unroll
    for (int nb = 0; nb < 2; nb++)
        boff[nb] = (uint32_t)((lane & 15) * (BSTR * 2) + (wn * 32 + nb * 16 + (lane >> 4) * 8) * 2);

    float acc0[2][4][4] = {}, acc1[2][4][4] = {};
    const int NC = NI / KC;

    float4 b0, b1, b2, b3;
    {
        CPA16(dA[0],      ip);
        CPA16(dA[0] + 16, ip + 8);
        CPA_COMMIT();
        b0 = *(const float4*)wbase;        b1 = *(const float4*)(wbase + 4);
        b2 = *(const float4*)(wbase + 64); b3 = *(const float4*)(wbase + 68);
        *(uint32_t*)&B0b[0][oB + 0] = pk2(b0.x, b0.y);
        *(uint32_t*)&B0b[0][oB + 2] = pk2(b0.z, b0.w);
        *(uint32_t*)&B0b[0][oB + 4] = pk2(b1.x, b1.y);
        *(uint32_t*)&B0b[0][oB + 6] = pk2(b1.z, b1.w);
        *(uint32_t*)&B1b[0][oB + 0] = pk2(b2.x, b2.y);
        *(uint32_t*)&B1b[0][oB + 2] = pk2(b2.z, b2.w);
        *(uint32_t*)&B1b[0][oB + 4] = pk2(b3.x, b3.y);
        *(uint32_t*)&B1b[0][oB + 6] = pk2(b3.z, b3.w);
        const float* pb = wbase + (size_t)KC * NH;
        b0 = *(const float4*)pb;        b1 = *(const float4*)(pb + 4);
        b2 = *(const float4*)(pb + 64); b3 = *(const float4*)(pb + 68);
    }
    CPA_WAIT0();
    __syncthreads();

    for (int c = 0; c < NC; c++) {
        int st = c & 1, ns = st ^ 1;
        if (c + 1 < NC) {
            const __half* pa = ip + (c + 1) * KC;
            CPA16(dA[ns],      pa);
            CPA16(dA[ns] + 16, pa + 8);
            *(uint32_t*)&B0b[ns][oB + 0] = pk2(b0.x, b0.y);
            *(uint32_t*)&B0b[ns][oB + 2] = pk2(b0.z, b0.w);
            *(uint32_t*)&B0b[ns][oB + 4] = pk2(b1.x, b1.y);
            *(uint32_t*)&B0b[ns][oB + 6] = pk2(b1.z, b1.w);
            *(uint32_t*)&B1b[ns][oB + 0] = pk2(b2.x, b2.y);
            *(uint32_t*)&B1b[ns][oB + 2] = pk2(b2.z, b2.w);
            *(uint32_t*)&B1b[ns][oB + 4] = pk2(b3.x, b3.y);
            *(uint32_t*)&B1b[ns][oB + 6] = pk2(b3.z, b3.w);
        }
        CPA_COMMIT();
        if (c + 2 < NC) {
            const float* pb = wbase + (size_t)((c + 2) * KC) * NH;
            b0 = *(const float4*)pb;        b1 = *(const float4*)(pb + 4);
            b2 = *(const float4*)(pb + 64); b3 = *(const float4*)(pb + 68);
        }
#pragma unroll
        for (int s = 0; s < 2; s++) {
            uint32_t ah[2][4], bb0[2][4], bb1[2][4];
            uint32_t as_ = (uint32_t)(s * 32), bs_ = (uint32_t)(s * 16 * BSTR * 2);
            ldm_x4(ah[0], sA[st] + aoff[0] + as_);
            ldm_x4(ah[1], sA[st] + aoff[1] + as_);
            ldm_x4t(bb0[0], sB0[st] + boff[0] + bs_);
            ldm_x4t(bb0[1], sB0[st] + boff[1] + bs_);
            ldm_x4t(bb1[0], sB1[st] + boff[0] + bs_);
            ldm_x4t(bb1[1], sB1[st] + boff[1] + bs_);
#pragma unroll
            for (int mf = 0; mf < 2; mf++)
#pragma unroll
                for (int nb = 0; nb < 2; nb++)
#pragma unroll
                    for (int f = 0; f < 2; f++) {
                        mma_fp16(acc0[mf][nb * 2 + f], ah[mf], &bb0[nb][f * 2]);
                        mma_fp16(acc1[mf][nb * 2 + f], ah[mf], &bb1[nb][f * 2]);
                    }
        }
        CPA_WAIT0();
        __syncthreads();
    }

#pragma unroll
    for (int mf = 0; mf < 2; mf++) {
        int rA = base + wm * 32 + mf * 16 + (lane >> 2);
        int tA = g_tok[rA], tB = g_tok[rA + 8];
        float* oa = out + (size_t)tA * NH;
        float* ob = out + (size_t)tB * NH;
#pragma unroll
        for (int nf = 0; nf < 4; nf++) {
            int col = n0 + wn * 32 + nf * 8 + (lane & 3) * 2;
            atomicAdd((float2*)(oa + col),      make_float2(acc0[mf][nf][0], acc0[mf][nf][1]));
            atomicAdd((float2*)(ob + col),      make_float2(acc0[mf][nf][2], acc0[mf][nf][3]));
            atomicAdd((float2*)(oa + col + 64), make_float2(acc1[mf][nf][0], acc1[mf][nf][1]));
            atomicAdd((float2*)(ob + col + 64), make_float2(acc1[mf][nf][2], acc1[mf][nf][3]));
        }
    }
}

// ---------------- launcher ----------------------------------------------------
extern "C" void kernel_launch(void* const* d_in, const int* in_sizes, int n_in,
                              void* d_out, int out_size) {
    const float* x   = (const float*)d_in[0];
    const int*   idx = (const int*)d_in[1];
    const float* w   = (const float*)d_in[2];
    const float* W1  = (const float*)d_in[3];
    const float* W2  = (const float*)d_in[4];
    float* out = (float*)d_out;

    k_xc<<<(NT * NH / 8) / 256, 256>>>(x, idx, out);
    k_r1<<<TKP / 256, 256>>>(idx);
    k_r2<<<1, 1024>>>(idx, w);

    dim3 g1(NI / 64, MAXTT);
    k_gemm1<<<g1, 256>>>(W1);

    dim3 g2(NH / 128, MAXTT);
    k_gemm2<<<g2, 256>>>(W2, out);
}